// round 1
// baseline (speedup 1.0000x reference)
#include <cuda_runtime.h>
#include <float.h>
#include <math.h>

// ---------------------------------------------------------------------------
// TS2Vec hierarchical loss, B=8, T=2048, C=64, ALPHA=0.5, TAU=0.1, EPS=1e-5
// ---------------------------------------------------------------------------

#define TTOP 2048
#define CDIM 64

// Scratch (no allocations allowed):
__device__ double g_acc;
__device__ __align__(16) float g_pyr[2][8 * 2047 * 64];   // pooled levels 1..11
__device__ float g_row_m[4094 * 16];                       // per-row online max (levels 0..10)
__device__ float g_row_d[4094 * 16];                       // per-row online denom

__device__ __forceinline__ int pyrOff(int l) {            // floats, l in [1,11]
    return 512 * (2048 - (4096 >> l));
}
__device__ __forceinline__ int rowOff(int l) {            // rows, l in [0,10]
    return 4096 - (4096 >> l);
}
__device__ __forceinline__ const float* lvl_base(int l, int b,
                                                 const float* z1, const float* z2) {
    int bb = b & 7;
    const float* z = (b < 8) ? z1 : z2;
    const float* p = (b < 8) ? g_pyr[0] : g_pyr[1];
    if (l == 0) return z + (size_t)bb * TTOP * CDIM;
    return p + pyrOff(l) + (size_t)bb * (size_t)(TTOP >> l) * CDIM;
}

// ---------------------------------------------------------------------------
__global__ void k_init() { g_acc = 0.0; }

// Pool levels 1..6 directly from the input (window max, window = 2^l <= 64).
__global__ void k_poolA(const float* __restrict__ z1, const float* __restrict__ z2) {
    int idx = blockIdx.x * blockDim.x + threadIdx.x;
    const int NPER = 512 * 2016;                 // sum_{l=1..6} 8*T_l*64
    if (idx >= 2 * NPER) return;
    int tensor = (idx >= NPER) ? 1 : 0;
    int off = idx - tensor * NPER;
    const float* in = tensor ? z2 : z1;
    int l = 1, T = 1024;
    while (off >= 512 * T) { off -= 512 * T; ++l; T >>= 1; }
    int c = off & 63;
    int t = (off >> 6) % T;
    int b = (off >> 6) / T;
    int w = TTOP / T;                            // 1<<l
    const float* src = in + ((size_t)b * TTOP + (size_t)t * w) * CDIM + c;
    float m = src[0];
    for (int k = 1; k < w; k++) m = fmaxf(m, src[(size_t)k * CDIM]);
    g_pyr[tensor][pyrOff(l) + ((size_t)b * T + t) * CDIM + c] = m;
}

// Pool levels 7..11 from level 6 (T6 = 32, window = 2^(l-6) <= 32).
__global__ void k_poolB() {
    int idx = blockIdx.x * blockDim.x + threadIdx.x;
    const int NPER = 512 * 31;                   // sum_{l=7..11} 8*T_l*64
    if (idx >= 2 * NPER) return;
    int tensor = (idx >= NPER) ? 1 : 0;
    int off = idx - tensor * NPER;
    int l = 7, T = 16;
    while (off >= 512 * T) { off -= 512 * T; ++l; T >>= 1; }
    int c = off & 63;
    int t = (off >> 6) % T;
    int b = (off >> 6) / T;
    int w = 32 / T;
    const float* src = g_pyr[tensor] + pyrOff(6) + ((size_t)b * 32 + (size_t)t * w) * CDIM + c;
    float m = src[0];
    for (int k = 1; k < w; k++) m = fmaxf(m, src[(size_t)k * CDIM]);
    g_pyr[tensor][pyrOff(l) + ((size_t)b * T + t) * CDIM + c] = m;
}

// ---------------------------------------------------------------------------
// Instance loss: one block per (level, t) slice. 4095 slices total.
// contribution weight per unit of blocksum: 1/(384*T_l)
__global__ void __launch_bounds__(256)
k_inst(const float* __restrict__ z1, const float* __restrict__ z2) {
    int slice = blockIdx.x;
    int l = 0, T = TTOP, t = slice;
    while (t >= T) { t -= T; ++l; T >>= 1; }

    __shared__ float zs[16][65];
    __shared__ float sim[16][17];
    __shared__ double bsum[16];
    int tid = threadIdx.x;

    for (int e = tid; e < 16 * 64; e += 256) {
        int r = e >> 6, c = e & 63;
        const float* rowp = lvl_base(l, r, z1, z2) + (size_t)t * CDIM;
        zs[r][c] = rowp[c];
    }
    __syncthreads();

    int i = tid >> 4, j = tid & 15;
    float acc = 0.f;
#pragma unroll
    for (int k = 0; k < 64; k++) acc += zs[i][k] * zs[j][k];
    sim[i][j] = acc;
    __syncthreads();

    if (tid < 16) {
        float m = -FLT_MAX;
#pragma unroll
        for (int jj = 0; jj < 16; jj++) if (jj != tid) m = fmaxf(m, sim[tid][jj]);
        float s = 0.f;
#pragma unroll
        for (int jj = 0; jj < 16; jj++) if (jj != tid) s += expf(sim[tid][jj] - m);
        float lse = m + logf(s);
        int pos = (tid < 8) ? tid + 8 : tid - 8;
        bsum[tid] = (double)(lse - sim[tid][pos]);
    }
    __syncthreads();
    if (tid == 0) {
        double tot = 0.0;
#pragma unroll
        for (int r = 0; r < 16; r++) tot += bsum[r];
        atomicAdd(&g_acc, tot / (384.0 * (double)T));
    }
}

// ---------------------------------------------------------------------------
// Temporal kernel A: Gram upper-triangle tiles + online row softmax + sum.
// Block = (level, b, xtile-pair). 64x64 tiles, 4x4 per-thread microtile.
#define PITCH 68

__device__ __forceinline__ void load_tile_T(float* dst, const float* zb,
                                            int r0, int T, int tid) {
    // dst[c*PITCH + r] = zb[(r0+r)*64 + c]
#pragma unroll
    for (int it = 0; it < 16; it++) {
        int e = tid + it * 256;
        int r = e >> 6, c = e & 63;
        float v = (r0 + r < T) ? zb[(size_t)(r0 + r) * CDIM + c] : 0.0f;
        dst[c * PITCH + r] = v;
    }
}

__global__ void __launch_bounds__(256)
k_tempA(const float* __restrict__ z1, const float* __restrict__ z2) {
    int bid = blockIdx.x;
    int l = 0, T = TTOP, npair;
    for (;;) {
        int nt = (T + 63) >> 6;
        npair = (nt + 1) >> 1;
        int cnt = 16 * npair;
        if (bid < cnt) break;
        bid -= cnt; ++l; T >>= 1;
    }
    int NT = (T + 63) >> 6;
    int b = bid / npair;
    int p = bid % npair;
    const float* zb = lvl_base(l, b, z1, z2);

    __shared__ float xs[64 * PITCH];
    __shared__ float ys[64 * PITCH];
    __shared__ float red_m[64 * 16];
    __shared__ float red_d[64 * 16];
    __shared__ double wsum[8];

    int tid = threadIdx.x;
    int tx = tid & 15, ty = tid >> 4;
    double Ssum = 0.0;

    int xtiles[2];
    int nxt = 1;
    xtiles[0] = p;
    if (NT - 1 - p != p) { xtiles[1] = NT - 1 - p; nxt = 2; }

    for (int xi = 0; xi < nxt; xi++) {
        int xt = xtiles[xi];
        int x0 = xt << 6;
        __syncthreads();                       // guard xs/red reuse
        load_tile_T(xs, zb, x0, T, tid);

        float m[4], d[4];
#pragma unroll
        for (int q = 0; q < 4; q++) { m[q] = -FLT_MAX; d[q] = 0.f; }

        for (int yt = xt; yt < NT; yt++) {
            int y0 = yt << 6;
            __syncthreads();                   // guard ys reuse (also covers xs load)
            load_tile_T(ys, zb, y0, T, tid);
            __syncthreads();

            float acc[4][4];
#pragma unroll
            for (int q = 0; q < 4; q++)
#pragma unroll
                for (int r = 0; r < 4; r++) acc[q][r] = 0.f;

#pragma unroll 8
            for (int k = 0; k < 64; k++) {
                float4 xv = *reinterpret_cast<const float4*>(&xs[k * PITCH + 4 * tx]);
                float4 yv = *reinterpret_cast<const float4*>(&ys[k * PITCH + 4 * ty]);
                acc[0][0] += xv.x * yv.x; acc[0][1] += xv.x * yv.y;
                acc[0][2] += xv.x * yv.z; acc[0][3] += xv.x * yv.w;
                acc[1][0] += xv.y * yv.x; acc[1][1] += xv.y * yv.y;
                acc[1][2] += xv.y * yv.z; acc[1][3] += xv.y * yv.w;
                acc[2][0] += xv.z * yv.x; acc[2][1] += xv.z * yv.y;
                acc[2][2] += xv.z * yv.z; acc[2][3] += xv.z * yv.w;
                acc[3][0] += xv.w * yv.x; acc[3][1] += xv.w * yv.y;
                acc[3][2] += xv.w * yv.z; acc[3][3] += xv.w * yv.w;
            }

#pragma unroll
            for (int q = 0; q < 4; q++) {
                int x = x0 + 4 * tx + q;
#pragma unroll
                for (int r = 0; r < 4; r++) {
                    int y = y0 + 4 * ty + r;
                    if (x < T && y < T && y > x) {
                        float s = acc[q][r] * 10.0f;    // /TAU
                        Ssum += (double)s;
                        if (s > m[q]) {
                            d[q] = d[q] * __expf(m[q] - s) + 1.0f;
                            m[q] = s;
                        } else {
                            d[q] += __expf(s - m[q]);
                        }
                    }
                }
            }
        }

        // combine 16 column-group partials per row, write (m,d) to global
        __syncthreads();
#pragma unroll
        for (int q = 0; q < 4; q++) {
            red_m[(4 * tx + q) * 16 + ty] = m[q];
            red_d[(4 * tx + q) * 16 + ty] = d[q];
        }
        __syncthreads();
        if (tid < 64) {
            float M = -FLT_MAX, D = 0.f;
#pragma unroll
            for (int s = 0; s < 16; s++) {
                float mm = red_m[tid * 16 + s];
                float dd = red_d[tid * 16 + s];
                if (mm > M) { D = D * __expf(M - mm) + dd; M = mm; }
                else        { D += dd * __expf(mm - M); }
            }
            int x = x0 + tid;
            if (x < T) {
                int idx = rowOff(l) * 16 + b * T + x;
                g_row_m[idx] = M;
                g_row_d[idx] = D;
            }
        }
    }

    // block-reduce Ssum (double), apply -S term with level weight
    double v = Ssum;
#pragma unroll
    for (int o = 16; o > 0; o >>= 1) v += __shfl_down_sync(0xffffffffu, v, o);
    if ((tid & 31) == 0) wsum[tid >> 5] = v;
    __syncthreads();
    if (tid == 0) {
        double tot = 0.0;
#pragma unroll
        for (int w = 0; w < 8; w++) tot += wsum[w];
        double wgt = 1.0 / (192.0 * (double)T * (double)(T - 1));
        atomicAdd(&g_acc, -wgt * tot);
    }
}

// ---------------------------------------------------------------------------
// Temporal kernel B: per (level,b) — global max M (rows + diagonal), then
// sum_x (T-1-x) * (M + log(d_x * exp(m_x - M) + eps))
__global__ void __launch_bounds__(256)
k_tempB(const float* __restrict__ z1, const float* __restrict__ z2) {
    int b = blockIdx.x;          // 0..15
    int l = blockIdx.y;          // 0..10
    int T = TTOP >> l;
    const float* zb = lvl_base(l, b, z1, z2);
    int base = rowOff(l) * 16 + b * T;
    int tid = threadIdx.x;

    __shared__ float smax[256];
    __shared__ double sd[256];

    float mloc = -FLT_MAX;
    for (int x = tid; x < T; x += 256) {
        const float4* row = reinterpret_cast<const float4*>(zb + (size_t)x * CDIM);
        float nrm = 0.f;
#pragma unroll
        for (int c = 0; c < 16; c++) {
            float4 vv = row[c];
            nrm += vv.x * vv.x + vv.y * vv.y + vv.z * vv.z + vv.w * vv.w;
        }
        mloc = fmaxf(mloc, fmaxf(nrm * 10.0f, g_row_m[base + x]));
    }
    smax[tid] = mloc;
    __syncthreads();
    for (int s = 128; s > 0; s >>= 1) {
        if (tid < s) smax[tid] = fmaxf(smax[tid], smax[tid + s]);
        __syncthreads();
    }
    float M = smax[0];

    double sum = 0.0;
    for (int x = tid; x < T; x += 256) {
        float mrow = g_row_m[base + x];
        float drow = g_row_d[base + x];
        float dg = drow * expf(mrow - M);
        float valrow = M + logf(dg + 1e-5f);
        sum += (double)(T - 1 - x) * (double)valrow;
    }
    sd[tid] = sum;
    __syncthreads();
    for (int s = 128; s > 0; s >>= 1) {
        if (tid < s) sd[tid] += sd[tid + s];
        __syncthreads();
    }
    if (tid == 0) {
        double wgt = 1.0 / (192.0 * (double)T * (double)(T - 1));
        atomicAdd(&g_acc, wgt * sd[0]);
    }
}

__global__ void k_fin(float* out) { out[0] = (float)g_acc; }

// ---------------------------------------------------------------------------
extern "C" void kernel_launch(void* const* d_in, const int* in_sizes, int n_in,
                              void* d_out, int out_size) {
    const float* z1 = (const float*)d_in[0];
    const float* z2 = (const float*)d_in[1];
    float* out = (float*)d_out;

    k_init<<<1, 1>>>();

    {
        int n = 2 * 512 * 2016;
        k_poolA<<<(n + 255) / 256, 256>>>(z1, z2);
    }
    {
        int n = 2 * 512 * 31;
        k_poolB<<<(n + 255) / 256, 256>>>();
    }

    k_inst<<<4095, 256>>>(z1, z2);

    // blocks: sum over levels 0..10 of 16 * npair = 16*37 = 592
    k_tempA<<<592, 256>>>(z1, z2);
    k_tempB<<<dim3(16, 11), 256>>>(z1, z2);

    k_fin<<<1, 1>>>(out);
}